// round 10
// baseline (speedup 1.0000x reference)
#include <cuda_runtime.h>
#include <cuda_bf16.h>
#include <math.h>
#include <stdint.h>

#define TT   2048
#define DD   768
#define NHH  12
#define HDD  64
#define LL   4
#define VV   32000

#define FLAG_GELU   1
#define FLAG_SPLIT  8

#define PRMT_HI 0x7632
#define PRMT_LO 0x5410

// ---------------- scratch ----------------
__device__ __align__(128) float    g_x    [TT * DD];
__device__ __align__(128) uint32_t g_h_s  [TT * DD];
__device__ __align__(128) float    g_qkv  [TT * 3 * DD];
__device__ __align__(128) uint32_t g_qkv_s[TT * 3 * DD];
__device__ __align__(128) uint32_t g_vt_s [NHH * HDD * TT];
__device__ __align__(128) uint32_t g_y_s  [TT * DD];
__device__ __align__(128) uint32_t g_m_s  [TT * 4 * DD];
// split weights (packed hi<<16|lo)
__device__ __align__(128) uint32_t g_ws_attn [LL * 3 * DD * DD];
__device__ __align__(128) uint32_t g_ws_aproj[LL * DD * DD];
__device__ __align__(128) uint32_t g_ws_fc   [LL * 4 * DD * DD];
__device__ __align__(128) uint32_t g_ws_proj [LL * DD * 4 * DD];
__device__ __align__(128) uint32_t g_ws_wte  [VV * DD];

// ---------------- helpers ----------------
__device__ __forceinline__ uint32_t prmt(uint32_t a, uint32_t b, uint32_t s) {
    uint32_t d;
    asm("prmt.b32 %0, %1, %2, %3;" : "=r"(d) : "r"(a), "r"(b), "r"(s));
    return d;
}

__device__ __forceinline__ uint32_t split_pack(float x) {
    __nv_bfloat16 h = __float2bfloat16(x);
    float r = x - __bfloat162float(h);
    __nv_bfloat16 l = __float2bfloat16(r);
    return ((uint32_t)__bfloat16_as_ushort(h) << 16) | (uint32_t)__bfloat16_as_ushort(l);
}

// pack two floats into A-frag style bf16x2 regs (hi pair, lo pair); low half = s0
__device__ __forceinline__ void split2pack(float s0, float s1, uint32_t& hi, uint32_t& lo) {
    __nv_bfloat16 h0 = __float2bfloat16(s0);
    __nv_bfloat16 h1 = __float2bfloat16(s1);
    __nv_bfloat16 l0 = __float2bfloat16(s0 - __bfloat162float(h0));
    __nv_bfloat16 l1 = __float2bfloat16(s1 - __bfloat162float(h1));
    hi = ((uint32_t)__bfloat16_as_ushort(h1) << 16) | (uint32_t)__bfloat16_as_ushort(h0);
    lo = ((uint32_t)__bfloat16_as_ushort(l1) << 16) | (uint32_t)__bfloat16_as_ushort(l0);
}

__device__ __forceinline__ uint32_t smem_u32(const void* p) {
    return (uint32_t)__cvta_generic_to_shared(p);
}

__device__ __forceinline__ void cp16(uint32_t saddr, const void* g) {
    asm volatile("cp.async.cg.shared.global [%0], [%1], 16;" :: "r"(saddr), "l"(g));
}
#define CP_COMMIT() asm volatile("cp.async.commit_group;")
#define CP_WAIT(n)  asm volatile("cp.async.wait_group %0;" :: "n"(n))

__device__ __forceinline__ void mma16816(float* c, const uint32_t* a, const uint32_t* b) {
    asm volatile(
        "mma.sync.aligned.m16n8k16.row.col.f32.bf16.bf16.f32 "
        "{%0,%1,%2,%3}, {%4,%5,%6,%7}, {%8,%9}, {%0,%1,%2,%3};"
        : "+f"(c[0]), "+f"(c[1]), "+f"(c[2]), "+f"(c[3])
        : "r"(a[0]), "r"(a[1]), "r"(a[2]), "r"(a[3]), "r"(b[0]), "r"(b[1]));
}

__device__ __forceinline__ float blockReduceSum256(float v, float* red) {
#pragma unroll
    for (int o = 16; o; o >>= 1) v += __shfl_xor_sync(0xffffffffu, v, o);
    if ((threadIdx.x & 31) == 0) red[threadIdx.x >> 5] = v;
    __syncthreads();
    float t = 0.f;
#pragma unroll
    for (int i = 0; i < 8; i++) t += red[i];
    __syncthreads();
    return t;
}

// ---------------- elementwise kernels ----------------
__global__ void split_kernel(const float4* __restrict__ src, uint4* __restrict__ dst, int n4) {
    int i = blockIdx.x * blockDim.x + threadIdx.x;
    if (i >= n4) return;
    float4 v = src[i];
    uint4 o;
    o.x = split_pack(v.x); o.y = split_pack(v.y);
    o.z = split_pack(v.z); o.w = split_pack(v.w);
    dst[i] = o;
}

__global__ void embed_kernel(const int* __restrict__ idx,
                             const float* __restrict__ wte,
                             float* __restrict__ x) {
    int t = blockIdx.x;
    long long v = idx[t];
    const float* src = wte + v * DD;
    float* dst = x + (long long)t * DD;
    for (int d = threadIdx.x; d < DD; d += blockDim.x) dst[d] = src[d];
}

__global__ void ln_split_kernel(const float* __restrict__ x,
                                const float* __restrict__ w,
                                uint32_t* __restrict__ out) {
    __shared__ float red[8];
    int t = blockIdx.x;
    const float* xr = x + (long long)t * DD;
    int tid = threadIdx.x;
    float v0 = xr[tid], v1 = xr[tid + 256], v2 = xr[tid + 512];
    float sum = blockReduceSum256(v0 + v1 + v2, red);
    float mu = sum * (1.0f / DD);
    float d0 = v0 - mu, d1 = v1 - mu, d2 = v2 - mu;
    float sq = blockReduceSum256(d0 * d0 + d1 * d1 + d2 * d2, red);
    float inv = rsqrtf(sq * (1.0f / DD) + 1e-5f);
    uint32_t* o = out + (long long)t * DD;
    o[tid]       = split_pack(d0 * inv * w[tid]);
    o[tid + 256] = split_pack(d1 * inv * w[tid + 256]);
    o[tid + 512] = split_pack(d2 * inv * w[tid + 512]);
}

// RoPE + split; q additionally scaled by 1/8 (softmax scale folded in)
__global__ void rope_split_kernel(const float* __restrict__ qkv,
                                  uint32_t* __restrict__ qkv_s) {
    int gid = blockIdx.x * blockDim.x + threadIdx.x;
    if (gid >= TT * NHH * 32) return;
    int d = gid & 31;
    int h = (gid >> 5) % NHH;
    int t = gid / (NHH * 32);
    float inv = expf(-logf(10000.0f) * (float)d / 32.0f);
    float fr = (float)t * inv;
    float s, c;
    sincosf(fr, &s, &c);
    long long base = (long long)t * (3 * DD) + h * HDD;
    const float* q = qkv + base;
    uint32_t* qs = qkv_s + base;
    float q1 = q[d], q2 = q[d + 32];
    qs[d]      = split_pack((q1 * c - q2 * s) * 0.125f);
    qs[d + 32] = split_pack((q1 * s + q2 * c) * 0.125f);
    const float* k = q + DD;
    uint32_t* ks = qs + DD;
    float k1 = k[d], k2 = k[d + 32];
    ks[d]      = split_pack(k1 * c - k2 * s);
    ks[d + 32] = split_pack(k1 * s + k2 * c);
}

__global__ void vsplit_t_kernel(const float* __restrict__ qkv,
                                uint32_t* __restrict__ vt) {
    int id = blockIdx.x * blockDim.x + threadIdx.x;
    if (id >= TT * DD) return;
    int t = id & (TT - 1);
    int dg = id >> 11;
    vt[(long long)dg * TT + t] =
        split_pack(qkv[(long long)t * (3 * DD) + 2 * DD + dg]);
}

// ---------------- bf16x3 mma.sync GEMM (weight GEMMs) ----------------
__global__ void __launch_bounds__(256, 1)
gemm3_kernel(const uint32_t* __restrict__ A, int lda,
             const uint32_t* __restrict__ B, int ldb,
             float* __restrict__ Cf, uint32_t* __restrict__ Cu,
             int ldc,
             const float* __restrict__ Cin, const float* __restrict__ bias,
             int K, int flags) {
    const int bx = blockIdx.x, by = blockIdx.y;
    const int nk = K >> 5;

    extern __shared__ uint32_t sm[];
    uint32_t* As[2] = { sm, sm + 5120 };
    uint32_t* Bs[2] = { sm + 10240, sm + 10240 + 5120 };

    const int tid = threadIdx.x;
    const int lane = tid & 31, warp = tid >> 5;
    const int warpM = warp >> 2, warpN = warp & 3;
    const int g = lane >> 2, t4 = lane & 3;
    const int rA = warpM * 64;
    const int cB = warpN * 32;

    const uint32_t* Abase = A + (long long)(by * 128) * lda;
    const uint32_t* Bbase = B + (long long)(bx * 128) * ldb;

    auto load_stage = [&](uint32_t* Ad, uint32_t* Bd, int kc) {
        const uint32_t* Ag = Abase + kc * 32;
        const uint32_t* Bg = Bbase + kc * 32;
#pragma unroll
        for (int i = 0; i < 4; i++) {
            int id = tid + i * 256;
            int r = id >> 3, c = (id & 7) * 4;
            cp16(smem_u32(Ad + r * 40 + c), Ag + (long long)r * lda + c);
            cp16(smem_u32(Bd + r * 40 + c), Bg + (long long)r * ldb + c);
        }
    };

    float acc[4][4][4];
#pragma unroll
    for (int i = 0; i < 4; i++)
#pragma unroll
        for (int j = 0; j < 4; j++)
#pragma unroll
            for (int r = 0; r < 4; r++) acc[i][j][r] = 0.f;

    load_stage(As[0], Bs[0], 0);
    CP_COMMIT();

    for (int kc = 0; kc < nk; kc++) {
        const int cur = kc & 1;
        if (kc + 1 < nk) {
            load_stage(As[cur ^ 1], Bs[cur ^ 1], kc + 1);
            CP_COMMIT();
            CP_WAIT(1);
        } else {
            CP_WAIT(0);
        }
        __syncthreads();

        const uint32_t* Ac = As[cur];
        const uint32_t* Bc = Bs[cur];

#pragma unroll
        for (int kb = 0; kb < 32; kb += 16) {
            uint32_t ah[4][4], al[4][4];
#pragma unroll
            for (int i = 0; i < 4; i++) {
                const uint32_t* base = Ac + (rA + i * 16 + g) * 40 + kb + 2 * t4;
                uint2 w01 = *(const uint2*)(base);
                uint2 w23 = *(const uint2*)(base + 8);
                uint2 w45 = *(const uint2*)(base + 8 * 40);
                uint2 w67 = *(const uint2*)(base + 8 * 40 + 8);
                ah[i][0] = prmt(w01.x, w01.y, PRMT_HI); al[i][0] = prmt(w01.x, w01.y, PRMT_LO);
                ah[i][1] = prmt(w45.x, w45.y, PRMT_HI); al[i][1] = prmt(w45.x, w45.y, PRMT_LO);
                ah[i][2] = prmt(w23.x, w23.y, PRMT_HI); al[i][2] = prmt(w23.x, w23.y, PRMT_LO);
                ah[i][3] = prmt(w67.x, w67.y, PRMT_HI); al[i][3] = prmt(w67.x, w67.y, PRMT_LO);
            }
            uint32_t bh[4][2], bl[4][2];
#pragma unroll
            for (int j = 0; j < 4; j++) {
                const uint32_t* base = Bc + (cB + j * 8 + g) * 40 + kb + 2 * t4;
                uint2 w01 = *(const uint2*)(base);
                uint2 w23 = *(const uint2*)(base + 8);
                bh[j][0] = prmt(w01.x, w01.y, PRMT_HI); bl[j][0] = prmt(w01.x, w01.y, PRMT_LO);
                bh[j][1] = prmt(w23.x, w23.y, PRMT_HI); bl[j][1] = prmt(w23.x, w23.y, PRMT_LO);
            }
#pragma unroll
            for (int i = 0; i < 4; i++)
#pragma unroll
                for (int j = 0; j < 4; j++) mma16816(acc[i][j], ah[i], bl[j]);
#pragma unroll
            for (int i = 0; i < 4; i++)
#pragma unroll
                for (int j = 0; j < 4; j++) mma16816(acc[i][j], al[i], bh[j]);
#pragma unroll
            for (int i = 0; i < 4; i++)
#pragma unroll
                for (int j = 0; j < 4; j++) mma16816(acc[i][j], ah[i], bh[j]);
        }
        __syncthreads();
    }

    const bool gelu = flags & FLAG_GELU;
    const bool splitout = flags & FLAG_SPLIT;
#pragma unroll
    for (int i = 0; i < 4; i++) {
        int r0 = by * 128 + rA + i * 16 + g;
#pragma unroll
        for (int j = 0; j < 4; j++) {
            int c0 = bx * 128 + cB + j * 8 + 2 * t4;
#pragma unroll
            for (int r = 0; r < 4; r++) {
                int row = r0 + (r >> 1) * 8;
                int col = c0 + (r & 1);
                float v = acc[i][j][r];
                if (bias) v += bias[col];
                if (gelu) v = 0.5f * v * (1.0f + erff(v * 0.70710678118654752f));
                long long cidx = (long long)row * ldc + col;
                if (Cin) v += Cin[cidx];
                if (splitout) Cu[cidx] = split_pack(v);
                else          Cf[cidx] = v;
            }
        }
    }
}

// ---------------- fused flash attention (bf16x3 mma.sync) ----------------
// grid: (T/128, NH). CTA: 8 warps; each warp owns 16 q-rows x all 64 d.
__global__ void __launch_bounds__(256, 1)
flash_kernel(const uint32_t* __restrict__ qkv_s,
             const uint32_t* __restrict__ vt_s,
             uint32_t* __restrict__ y_s) {
    const int qb = (int)(gridDim.x - 1) - blockIdx.x;   // heavy blocks first
    const int h  = blockIdx.y;

    extern __shared__ uint32_t sm[];
    uint32_t* Qs = sm;                                   // 128 x 72
    uint32_t* Ks[2] = { sm + 9216, sm + 9216 + 9216 };   // 128 x 72 each
    uint32_t* Vs[2] = { sm + 27648, sm + 27648 + 8704 }; // 64 x 136 each

    const int tid = threadIdx.x;
    const int lane = tid & 31, warp = tid >> 5;
    const int g = lane >> 2, t4 = lane & 3;

    const uint32_t* Qg = qkv_s + (long long)(qb * 128) * (3 * DD) + h * HDD;
    const uint32_t* Kg = qkv_s + DD + h * HDD;
    const uint32_t* Vg = vt_s + (long long)(h * HDD) * TT;

    auto loadKV = [&](int buf, int kb) {
        const uint32_t* kg = Kg + (long long)(kb * 128) * (3 * DD);
#pragma unroll
        for (int i = 0; i < 8; i++) {
            int id = tid + i * 256;
            int r = id >> 4, c = (id & 15) * 4;
            cp16(smem_u32(Ks[buf] + r * 72 + c), kg + (long long)r * (3 * DD) + c);
        }
        const uint32_t* vg = Vg + kb * 128;
#pragma unroll
        for (int i = 0; i < 8; i++) {
            int id = tid + i * 256;
            int r = id >> 5, c = (id & 31) * 4;
            cp16(smem_u32(Vs[buf] + r * 136 + c), vg + (long long)r * TT + c);
        }
    };

    // load Q + first K/V block
#pragma unroll
    for (int i = 0; i < 8; i++) {
        int id = tid + i * 256;
        int r = id >> 4, c = (id & 15) * 4;
        cp16(smem_u32(Qs + r * 72 + c), Qg + (long long)r * (3 * DD) + c);
    }
    loadKV(0, 0);
    CP_COMMIT();
    CP_WAIT(0);
    __syncthreads();

    // Q fragments (persistent)
    uint32_t qh[4][4], ql[4][4];
#pragma unroll
    for (int ks = 0; ks < 4; ks++) {
        const uint32_t* base = Qs + (warp * 16 + g) * 72 + ks * 16 + 2 * t4;
        uint2 w01 = *(const uint2*)(base);
        uint2 w23 = *(const uint2*)(base + 8);
        uint2 w45 = *(const uint2*)(base + 8 * 72);
        uint2 w67 = *(const uint2*)(base + 8 * 72 + 8);
        qh[ks][0] = prmt(w01.x, w01.y, PRMT_HI); ql[ks][0] = prmt(w01.x, w01.y, PRMT_LO);
        qh[ks][1] = prmt(w45.x, w45.y, PRMT_HI); ql[ks][1] = prmt(w45.x, w45.y, PRMT_LO);
        qh[ks][2] = prmt(w23.x, w23.y, PRMT_HI); ql[ks][2] = prmt(w23.x, w23.y, PRMT_LO);
        qh[ks][3] = prmt(w67.x, w67.y, PRMT_HI); ql[ks][3] = prmt(w67.x, w67.y, PRMT_LO);
    }

    float o[8][4];
#pragma unroll
    for (int j = 0; j < 8; j++)
#pragma unroll
        for (int r = 0; r < 4; r++) o[j][r] = 0.f;
    float mrow[2] = { -INFINITY, -INFINITY };
    float lrow[2] = { 0.f, 0.f };

    for (int kb = 0; kb <= qb; kb++) {
        const int buf = kb & 1;
        if (kb < qb) {
            loadKV(buf ^ 1, kb + 1);
            CP_COMMIT();
            CP_WAIT(1);
        } else {
            CP_WAIT(0);
        }
        __syncthreads();

        // S = Q @ K^T  (16 n-tiles of 8)
        float s[16][4];
#pragma unroll
        for (int j = 0; j < 16; j++)
#pragma unroll
            for (int r = 0; r < 4; r++) s[j][r] = 0.f;

#pragma unroll
        for (int ks = 0; ks < 4; ks++) {
#pragma unroll
            for (int jn = 0; jn < 16; jn++) {
                const uint32_t* b = Ks[buf] + (jn * 8 + g) * 72 + ks * 16 + 2 * t4;
                uint2 w01 = *(const uint2*)(b);
                uint2 w23 = *(const uint2*)(b + 8);
                uint32_t bh[2] = { prmt(w01.x, w01.y, PRMT_HI), prmt(w23.x, w23.y, PRMT_HI) };
                uint32_t bl[2] = { prmt(w01.x, w01.y, PRMT_LO), prmt(w23.x, w23.y, PRMT_LO) };
                mma16816(s[jn], qh[ks], bl);
                mma16816(s[jn], ql[ks], bh);
                mma16816(s[jn], qh[ks], bh);
            }
        }

        // causal mask on diagonal block
        if (kb == qb) {
            const int rowg = qb * 128 + warp * 16 + g;
#pragma unroll
            for (int jn = 0; jn < 16; jn++) {
                int col = kb * 128 + jn * 8 + 2 * t4;
                if (col     > rowg)     s[jn][0] = -INFINITY;
                if (col + 1 > rowg)     s[jn][1] = -INFINITY;
                if (col     > rowg + 8) s[jn][2] = -INFINITY;
                if (col + 1 > rowg + 8) s[jn][3] = -INFINITY;
            }
        }

        // online softmax (two rows per thread: g and g+8)
        float pcorr[2];
#pragma unroll
        for (int r2 = 0; r2 < 2; r2++) {
            float mx = -INFINITY;
#pragma unroll
            for (int jn = 0; jn < 16; jn++)
                mx = fmaxf(mx, fmaxf(s[jn][2 * r2], s[jn][2 * r2 + 1]));
            mx = fmaxf(mx, __shfl_xor_sync(0xffffffffu, mx, 1));
            mx = fmaxf(mx, __shfl_xor_sync(0xffffffffu, mx, 2));
            float mnew = fmaxf(mrow[r2], mx);
            float corr = __expf(mrow[r2] - mnew);
            mrow[r2] = mnew;
            pcorr[r2] = corr;
            float sum = 0.f;
#pragma unroll
            for (int jn = 0; jn < 16; jn++) {
                float p0 = __expf(s[jn][2 * r2]     - mnew);
                float p1 = __expf(s[jn][2 * r2 + 1] - mnew);
                s[jn][2 * r2] = p0; s[jn][2 * r2 + 1] = p1;
                sum += p0 + p1;
            }
            sum += __shfl_xor_sync(0xffffffffu, sum, 1);
            sum += __shfl_xor_sync(0xffffffffu, sum, 2);
            lrow[r2] = lrow[r2] * corr + sum;
        }
#pragma unroll
        for (int j = 0; j < 8; j++) {
            o[j][0] *= pcorr[0]; o[j][1] *= pcorr[0];
            o[j][2] *= pcorr[1]; o[j][3] *= pcorr[1];
        }

        // PV: A = P (regs), B = V^T tile from smem
#pragma unroll
        for (int ks = 0; ks < 8; ks++) {
            uint32_t ph[4], pl[4];
            split2pack(s[2 * ks][0],     s[2 * ks][1],     ph[0], pl[0]);
            split2pack(s[2 * ks][2],     s[2 * ks][3],     ph[1], pl[1]);
            split2pack(s[2 * ks + 1][0], s[2 * ks + 1][1], ph[2], pl[2]);
            split2pack(s[2 * ks + 1][2], s[2 * ks + 1][3], ph[3], pl[3]);
#pragma unroll
            for (int j2 = 0; j2 < 8; j2++) {
                const uint32_t* b = Vs[buf] + (j2 * 8 + g) * 136 + ks * 16 + 2 * t4;
                uint2 w01 = *(const uint2*)(b);
                uint2 w23 = *(const uint2*)(b + 8);
                uint32_t bh[2] = { prmt(w01.x, w01.y, PRMT_HI), prmt(w23.x, w23.y, PRMT_HI) };
                uint32_t bl[2] = { prmt(w01.x, w01.y, PRMT_LO), prmt(w23.x, w23.y, PRMT_LO) };
                mma16816(o[j2], ph, bl);
                mma16816(o[j2], pl, bh);
                mma16816(o[j2], ph, bh);
            }
        }
        __syncthreads();
    }

    // epilogue: y = o / l, write packed split
    const float inv0 = 1.0f / lrow[0];
    const float inv1 = 1.0f / lrow[1];
    const int row0 = qb * 128 + warp * 16 + g;
#pragma unroll
    for (int j2 = 0; j2 < 8; j2++) {
        int col = h * HDD + j2 * 8 + 2 * t4;
        y_s[(long long)row0 * DD + col]           = split_pack(o[j2][0] * inv0);
        y_s[(long long)row0 * DD + col + 1]       = split_pack(o[j2][1] * inv0);
        y_s[(long long)(row0 + 8) * DD + col]     = split_pack(o[j2][2] * inv1);
        y_s[(long long)(row0 + 8) * DD + col + 1] = split_pack(o[j2][3] * inv1);
    }
}

// ---------------- launch ----------------
extern "C" void kernel_launch(void* const* d_in, const int* in_sizes, int n_in,
                              void* d_out, int out_size) {
    const int*   idx        = (const int*)  d_in[0];
    const float* wte        = (const float*)d_in[1];
    const float* ln1_w      = (const float*)d_in[2];
    const float* attn_w     = (const float*)d_in[3];
    const float* attnproj_w = (const float*)d_in[4];
    const float* ln2_w      = (const float*)d_in[5];
    const float* fc_w       = (const float*)d_in[6];
    const float* fc_b       = (const float*)d_in[7];
    const float* proj_w     = (const float*)d_in[8];
    const float* proj_b     = (const float*)d_in[9];
    const float* lnf_w      = (const float*)d_in[10];
    const float* unemb_b    = (const float*)d_in[11];
    float* out = (float*)d_out;

    float *px, *pqkv;
    uint32_t *ph_s, *pqkv_s, *pvt_s, *py_s, *pm_s;
    uint32_t *pw_attn, *pw_aproj, *pw_fc, *pw_proj, *pw_wte;
    cudaGetSymbolAddress((void**)&px,      g_x);
    cudaGetSymbolAddress((void**)&ph_s,    g_h_s);
    cudaGetSymbolAddress((void**)&pqkv,    g_qkv);
    cudaGetSymbolAddress((void**)&pqkv_s,  g_qkv_s);
    cudaGetSymbolAddress((void**)&pvt_s,   g_vt_s);
    cudaGetSymbolAddress((void**)&py_s,    g_y_s);
    cudaGetSymbolAddress((void**)&pm_s,    g_m_s);
    cudaGetSymbolAddress((void**)&pw_attn,  g_ws_attn);
    cudaGetSymbolAddress((void**)&pw_aproj, g_ws_aproj);
    cudaGetSymbolAddress((void**)&pw_fc,    g_ws_fc);
    cudaGetSymbolAddress((void**)&pw_proj,  g_ws_proj);
    cudaGetSymbolAddress((void**)&pw_wte,   g_ws_wte);

    const int SM_GEMM  = 4 * 5120 * 4;               // 81920
    const int SM_FLASH = (9216 + 2 * 9216 + 2 * 8704) * 4;  // 180224
    cudaFuncSetAttribute(gemm3_kernel, cudaFuncAttributeMaxDynamicSharedMemorySize, SM_GEMM);
    cudaFuncSetAttribute(flash_kernel, cudaFuncAttributeMaxDynamicSharedMemorySize, SM_FLASH);

    auto split = [&](const float* s, uint32_t* d, long long n) {
        int n4 = (int)(n / 4);
        split_kernel<<<(n4 + 255) / 256, 256>>>((const float4*)s, (uint4*)d, n4);
    };
    split(attn_w,     pw_attn,  (long long)LL * 3 * DD * DD);
    split(attnproj_w, pw_aproj, (long long)LL * DD * DD);
    split(fc_w,       pw_fc,    (long long)LL * 4 * DD * DD);
    split(proj_w,     pw_proj,  (long long)LL * DD * 4 * DD);
    split(wte,        pw_wte,   (long long)VV * DD);

    embed_kernel<<<TT, 256>>>(idx, wte, px);

    for (int l = 0; l < LL; l++) {
        ln_split_kernel<<<TT, 256>>>(px, ln1_w + l * DD, ph_s);

        // QKV
        gemm3_kernel<<<dim3(3 * DD / 128, TT / 128), 256, SM_GEMM>>>(
            ph_s, DD, pw_attn + (long long)l * 3 * DD * DD, DD,
            pqkv, nullptr, 3 * DD, nullptr, nullptr, DD, 0);

        rope_split_kernel<<<(TT * NHH * 32 + 255) / 256, 256>>>(pqkv, pqkv_s);
        vsplit_t_kernel<<<(TT * DD + 255) / 256, 256>>>(pqkv, pvt_s);

        // fused attention -> y_s (packed)
        flash_kernel<<<dim3(TT / 128, NHH), 256, SM_FLASH>>>(pqkv_s, pvt_s, py_s);

        // x += y @ attnproj^T
        gemm3_kernel<<<dim3(DD / 128, TT / 128), 256, SM_GEMM>>>(
            py_s, DD, pw_aproj + (long long)l * DD * DD, DD,
            px, nullptr, DD, px, nullptr, DD, 0);

        ln_split_kernel<<<TT, 256>>>(px, ln2_w + l * DD, ph_s);

        // m = gelu(h @ fc^T + b) -> packed
        gemm3_kernel<<<dim3(4 * DD / 128, TT / 128), 256, SM_GEMM>>>(
            ph_s, DD, pw_fc + (long long)l * 4 * DD * DD, DD,
            nullptr, pm_s, 4 * DD, nullptr, fc_b + (long long)l * 4 * DD, DD,
            FLAG_GELU | FLAG_SPLIT);

        // x += m @ proj^T + b
        gemm3_kernel<<<dim3(DD / 128, TT / 128), 256, SM_GEMM>>>(
            pm_s, 4 * DD, pw_proj + (long long)l * DD * 4 * DD, 4 * DD,
            px, nullptr, DD, px, proj_b + (long long)l * DD, 4 * DD, 0);
    }

    ln_split_kernel<<<TT, 256>>>(px, lnf_w, ph_s);

    // logits
    gemm3_kernel<<<dim3(VV / 128, TT / 128), 256, SM_GEMM>>>(
        ph_s, DD, pw_wte, DD,
        out, nullptr, VV, nullptr, unemb_b, DD, 0);
}

// round 11
// speedup vs baseline: 1.5292x; 1.5292x over previous
#include <cuda_runtime.h>
#include <cuda_bf16.h>
#include <math.h>
#include <stdint.h>

#define TT   2048
#define DD   768
#define NHH  12
#define HDD  64
#define LL   4
#define VV   32000

#define FLAG_GELU   1
#define FLAG_SPLIT  8

#define PRMT_HI 0x7632
#define PRMT_LO 0x5410

// ---------------- scratch ----------------
__device__ __align__(128) float    g_x    [TT * DD];
__device__ __align__(128) uint32_t g_h_s  [TT * DD];
__device__ __align__(128) float    g_qkv  [TT * 3 * DD];
__device__ __align__(128) uint32_t g_qkv_s[TT * 3 * DD];
__device__ __align__(128) uint32_t g_vt_s [NHH * HDD * TT];
__device__ __align__(128) uint32_t g_y_s  [TT * DD];
__device__ __align__(128) uint32_t g_m_s  [TT * 4 * DD];
// split weights (packed hi<<16|lo)
__device__ __align__(128) uint32_t g_ws_attn [LL * 3 * DD * DD];
__device__ __align__(128) uint32_t g_ws_aproj[LL * DD * DD];
__device__ __align__(128) uint32_t g_ws_fc   [LL * 4 * DD * DD];
__device__ __align__(128) uint32_t g_ws_proj [LL * DD * 4 * DD];
__device__ __align__(128) uint32_t g_ws_wte  [VV * DD];

// ---------------- helpers ----------------
__device__ __forceinline__ uint32_t prmt(uint32_t a, uint32_t b, uint32_t s) {
    uint32_t d;
    asm("prmt.b32 %0, %1, %2, %3;" : "=r"(d) : "r"(a), "r"(b), "r"(s));
    return d;
}

__device__ __forceinline__ uint32_t split_pack(float x) {
    __nv_bfloat16 h = __float2bfloat16(x);
    float r = x - __bfloat162float(h);
    __nv_bfloat16 l = __float2bfloat16(r);
    return ((uint32_t)__bfloat16_as_ushort(h) << 16) | (uint32_t)__bfloat16_as_ushort(l);
}

// pack two floats into A-frag style bf16x2 regs (hi pair, lo pair); low half = s0
__device__ __forceinline__ void split2pack(float s0, float s1, uint32_t& hi, uint32_t& lo) {
    __nv_bfloat16 h0 = __float2bfloat16(s0);
    __nv_bfloat16 h1 = __float2bfloat16(s1);
    __nv_bfloat16 l0 = __float2bfloat16(s0 - __bfloat162float(h0));
    __nv_bfloat16 l1 = __float2bfloat16(s1 - __bfloat162float(h1));
    hi = ((uint32_t)__bfloat16_as_ushort(h1) << 16) | (uint32_t)__bfloat16_as_ushort(h0);
    lo = ((uint32_t)__bfloat16_as_ushort(l1) << 16) | (uint32_t)__bfloat16_as_ushort(l0);
}

__device__ __forceinline__ uint32_t smem_u32(const void* p) {
    return (uint32_t)__cvta_generic_to_shared(p);
}

__device__ __forceinline__ void cp16(uint32_t saddr, const void* g) {
    asm volatile("cp.async.cg.shared.global [%0], [%1], 16;" :: "r"(saddr), "l"(g));
}
#define CP_COMMIT() asm volatile("cp.async.commit_group;")
#define CP_WAIT(n)  asm volatile("cp.async.wait_group %0;" :: "n"(n))

__device__ __forceinline__ void mma16816(float* c, const uint32_t* a, const uint32_t* b) {
    asm volatile(
        "mma.sync.aligned.m16n8k16.row.col.f32.bf16.bf16.f32 "
        "{%0,%1,%2,%3}, {%4,%5,%6,%7}, {%8,%9}, {%0,%1,%2,%3};"
        : "+f"(c[0]), "+f"(c[1]), "+f"(c[2]), "+f"(c[3])
        : "r"(a[0]), "r"(a[1]), "r"(a[2]), "r"(a[3]), "r"(b[0]), "r"(b[1]));
}

__device__ __forceinline__ float blockReduceSum256(float v, float* red) {
#pragma unroll
    for (int o = 16; o; o >>= 1) v += __shfl_xor_sync(0xffffffffu, v, o);
    if ((threadIdx.x & 31) == 0) red[threadIdx.x >> 5] = v;
    __syncthreads();
    float t = 0.f;
#pragma unroll
    for (int i = 0; i < 8; i++) t += red[i];
    __syncthreads();
    return t;
}

// ---------------- elementwise kernels ----------------
__global__ void split_kernel(const float4* __restrict__ src, uint4* __restrict__ dst, int n4) {
    int i = blockIdx.x * blockDim.x + threadIdx.x;
    if (i >= n4) return;
    float4 v = src[i];
    uint4 o;
    o.x = split_pack(v.x); o.y = split_pack(v.y);
    o.z = split_pack(v.z); o.w = split_pack(v.w);
    dst[i] = o;
}

__global__ void embed_kernel(const int* __restrict__ idx,
                             const float* __restrict__ wte,
                             float* __restrict__ x) {
    int t = blockIdx.x;
    long long v = idx[t];
    const float* src = wte + v * DD;
    float* dst = x + (long long)t * DD;
    for (int d = threadIdx.x; d < DD; d += blockDim.x) dst[d] = src[d];
}

__global__ void ln_split_kernel(const float* __restrict__ x,
                                const float* __restrict__ w,
                                uint32_t* __restrict__ out) {
    __shared__ float red[8];
    int t = blockIdx.x;
    const float* xr = x + (long long)t * DD;
    int tid = threadIdx.x;
    float v0 = xr[tid], v1 = xr[tid + 256], v2 = xr[tid + 512];
    float sum = blockReduceSum256(v0 + v1 + v2, red);
    float mu = sum * (1.0f / DD);
    float d0 = v0 - mu, d1 = v1 - mu, d2 = v2 - mu;
    float sq = blockReduceSum256(d0 * d0 + d1 * d1 + d2 * d2, red);
    float inv = rsqrtf(sq * (1.0f / DD) + 1e-5f);
    uint32_t* o = out + (long long)t * DD;
    o[tid]       = split_pack(d0 * inv * w[tid]);
    o[tid + 256] = split_pack(d1 * inv * w[tid + 256]);
    o[tid + 512] = split_pack(d2 * inv * w[tid + 512]);
}

// RoPE + split; q additionally scaled by 1/8 (softmax scale folded in)
__global__ void rope_split_kernel(const float* __restrict__ qkv,
                                  uint32_t* __restrict__ qkv_s) {
    int gid = blockIdx.x * blockDim.x + threadIdx.x;
    if (gid >= TT * NHH * 32) return;
    int d = gid & 31;
    int h = (gid >> 5) % NHH;
    int t = gid / (NHH * 32);
    float inv = expf(-logf(10000.0f) * (float)d / 32.0f);
    float fr = (float)t * inv;
    float s, c;
    sincosf(fr, &s, &c);
    long long base = (long long)t * (3 * DD) + h * HDD;
    const float* q = qkv + base;
    uint32_t* qs = qkv_s + base;
    float q1 = q[d], q2 = q[d + 32];
    qs[d]      = split_pack((q1 * c - q2 * s) * 0.125f);
    qs[d + 32] = split_pack((q1 * s + q2 * c) * 0.125f);
    const float* k = q + DD;
    uint32_t* ks = qs + DD;
    float k1 = k[d], k2 = k[d + 32];
    ks[d]      = split_pack(k1 * c - k2 * s);
    ks[d + 32] = split_pack(k1 * s + k2 * c);
}

__global__ void vsplit_t_kernel(const float* __restrict__ qkv,
                                uint32_t* __restrict__ vt) {
    int id = blockIdx.x * blockDim.x + threadIdx.x;
    if (id >= TT * DD) return;
    int t = id & (TT - 1);
    int dg = id >> 11;
    vt[(long long)dg * TT + t] =
        split_pack(qkv[(long long)t * (3 * DD) + 2 * DD + dg]);
}

// ---------------- bf16x3 mma.sync GEMM (weight GEMMs) ----------------
__global__ void __launch_bounds__(256, 1)
gemm3_kernel(const uint32_t* __restrict__ A, int lda,
             const uint32_t* __restrict__ B, int ldb,
             float* __restrict__ Cf, uint32_t* __restrict__ Cu,
             int ldc,
             const float* __restrict__ Cin, const float* __restrict__ bias,
             int K, int flags) {
    const int bx = blockIdx.x, by = blockIdx.y;
    const int nk = K >> 5;

    extern __shared__ uint32_t sm[];
    uint32_t* As[2] = { sm, sm + 5120 };
    uint32_t* Bs[2] = { sm + 10240, sm + 10240 + 5120 };

    const int tid = threadIdx.x;
    const int lane = tid & 31, warp = tid >> 5;
    const int warpM = warp >> 2, warpN = warp & 3;
    const int g = lane >> 2, t4 = lane & 3;
    const int rA = warpM * 64;
    const int cB = warpN * 32;

    const uint32_t* Abase = A + (long long)(by * 128) * lda;
    const uint32_t* Bbase = B + (long long)(bx * 128) * ldb;

    auto load_stage = [&](uint32_t* Ad, uint32_t* Bd, int kc) {
        const uint32_t* Ag = Abase + kc * 32;
        const uint32_t* Bg = Bbase + kc * 32;
#pragma unroll
        for (int i = 0; i < 4; i++) {
            int id = tid + i * 256;
            int r = id >> 3, c = (id & 7) * 4;
            cp16(smem_u32(Ad + r * 40 + c), Ag + (long long)r * lda + c);
            cp16(smem_u32(Bd + r * 40 + c), Bg + (long long)r * ldb + c);
        }
    };

    float acc[4][4][4];
#pragma unroll
    for (int i = 0; i < 4; i++)
#pragma unroll
        for (int j = 0; j < 4; j++)
#pragma unroll
            for (int r = 0; r < 4; r++) acc[i][j][r] = 0.f;

    load_stage(As[0], Bs[0], 0);
    CP_COMMIT();

    for (int kc = 0; kc < nk; kc++) {
        const int cur = kc & 1;
        if (kc + 1 < nk) {
            load_stage(As[cur ^ 1], Bs[cur ^ 1], kc + 1);
            CP_COMMIT();
            CP_WAIT(1);
        } else {
            CP_WAIT(0);
        }
        __syncthreads();

        const uint32_t* Ac = As[cur];
        const uint32_t* Bc = Bs[cur];

#pragma unroll
        for (int kb = 0; kb < 32; kb += 16) {
            uint32_t ah[4][4], al[4][4];
#pragma unroll
            for (int i = 0; i < 4; i++) {
                const uint32_t* base = Ac + (rA + i * 16 + g) * 40 + kb + 2 * t4;
                uint2 w01 = *(const uint2*)(base);
                uint2 w23 = *(const uint2*)(base + 8);
                uint2 w45 = *(const uint2*)(base + 8 * 40);
                uint2 w67 = *(const uint2*)(base + 8 * 40 + 8);
                ah[i][0] = prmt(w01.x, w01.y, PRMT_HI); al[i][0] = prmt(w01.x, w01.y, PRMT_LO);
                ah[i][1] = prmt(w45.x, w45.y, PRMT_HI); al[i][1] = prmt(w45.x, w45.y, PRMT_LO);
                ah[i][2] = prmt(w23.x, w23.y, PRMT_HI); al[i][2] = prmt(w23.x, w23.y, PRMT_LO);
                ah[i][3] = prmt(w67.x, w67.y, PRMT_HI); al[i][3] = prmt(w67.x, w67.y, PRMT_LO);
            }
            uint32_t bh[4][2], bl[4][2];
#pragma unroll
            for (int j = 0; j < 4; j++) {
                const uint32_t* base = Bc + (cB + j * 8 + g) * 40 + kb + 2 * t4;
                uint2 w01 = *(const uint2*)(base);
                uint2 w23 = *(const uint2*)(base + 8);
                bh[j][0] = prmt(w01.x, w01.y, PRMT_HI); bl[j][0] = prmt(w01.x, w01.y, PRMT_LO);
                bh[j][1] = prmt(w23.x, w23.y, PRMT_HI); bl[j][1] = prmt(w23.x, w23.y, PRMT_LO);
            }
#pragma unroll
            for (int i = 0; i < 4; i++)
#pragma unroll
                for (int j = 0; j < 4; j++) mma16816(acc[i][j], ah[i], bl[j]);
#pragma unroll
            for (int i = 0; i < 4; i++)
#pragma unroll
                for (int j = 0; j < 4; j++) mma16816(acc[i][j], al[i], bh[j]);
#pragma unroll
            for (int i = 0; i < 4; i++)
#pragma unroll
                for (int j = 0; j < 4; j++) mma16816(acc[i][j], ah[i], bh[j]);
        }
        __syncthreads();
    }

    const bool gelu = flags & FLAG_GELU;
    const bool splitout = flags & FLAG_SPLIT;
#pragma unroll
    for (int i = 0; i < 4; i++) {
        int r0 = by * 128 + rA + i * 16 + g;
#pragma unroll
        for (int j = 0; j < 4; j++) {
            int c0 = bx * 128 + cB + j * 8 + 2 * t4;
#pragma unroll
            for (int r = 0; r < 4; r++) {
                int row = r0 + (r >> 1) * 8;
                int col = c0 + (r & 1);
                float v = acc[i][j][r];
                if (bias) v += bias[col];
                if (gelu) v = 0.5f * v * (1.0f + erff(v * 0.70710678118654752f));
                long long cidx = (long long)row * ldc + col;
                if (Cin) v += Cin[cidx];
                if (splitout) Cu[cidx] = split_pack(v);
                else          Cf[cidx] = v;
            }
        }
    }
}

// ---------------- fused flash attention (bf16x3 mma.sync) ----------------
// grid: (T/128, NH). CTA: 8 warps; each warp owns 16 q-rows x all 64 d.
__global__ void __launch_bounds__(256, 1)
flash_kernel(const uint32_t* __restrict__ qkv_s,
             const uint32_t* __restrict__ vt_s,
             uint32_t* __restrict__ y_s) {
    const int qb = (int)(gridDim.x - 1) - blockIdx.x;   // heavy blocks first
    const int h  = blockIdx.y;

    extern __shared__ uint32_t sm[];
    uint32_t* Qs = sm;                                   // 128 x 72
    uint32_t* Ks[2] = { sm + 9216, sm + 9216 + 9216 };   // 128 x 72 each
    uint32_t* Vs[2] = { sm + 27648, sm + 27648 + 8704 }; // 64 x 136 each

    const int tid = threadIdx.x;
    const int lane = tid & 31, warp = tid >> 5;
    const int g = lane >> 2, t4 = lane & 3;

    const uint32_t* Qg = qkv_s + (long long)(qb * 128) * (3 * DD) + h * HDD;
    const uint32_t* Kg = qkv_s + DD + h * HDD;
    const uint32_t* Vg = vt_s + (long long)(h * HDD) * TT;

    auto loadKV = [&](int buf, int kb) {
        const uint32_t* kg = Kg + (long long)(kb * 128) * (3 * DD);
#pragma unroll
        for (int i = 0; i < 8; i++) {
            int id = tid + i * 256;
            int r = id >> 4, c = (id & 15) * 4;
            cp16(smem_u32(Ks[buf] + r * 72 + c), kg + (long long)r * (3 * DD) + c);
        }
        const uint32_t* vg = Vg + kb * 128;
#pragma unroll
        for (int i = 0; i < 8; i++) {
            int id = tid + i * 256;
            int r = id >> 5, c = (id & 31) * 4;
            cp16(smem_u32(Vs[buf] + r * 136 + c), vg + (long long)r * TT + c);
        }
    };

    // load Q + first K/V block
#pragma unroll
    for (int i = 0; i < 8; i++) {
        int id = tid + i * 256;
        int r = id >> 4, c = (id & 15) * 4;
        cp16(smem_u32(Qs + r * 72 + c), Qg + (long long)r * (3 * DD) + c);
    }
    loadKV(0, 0);
    CP_COMMIT();
    CP_WAIT(0);
    __syncthreads();

    // Q fragments (persistent)
    uint32_t qh[4][4], ql[4][4];
#pragma unroll
    for (int ks = 0; ks < 4; ks++) {
        const uint32_t* base = Qs + (warp * 16 + g) * 72 + ks * 16 + 2 * t4;
        uint2 w01 = *(const uint2*)(base);
        uint2 w23 = *(const uint2*)(base + 8);
        uint2 w45 = *(const uint2*)(base + 8 * 72);
        uint2 w67 = *(const uint2*)(base + 8 * 72 + 8);
        qh[ks][0] = prmt(w01.x, w01.y, PRMT_HI); ql[ks][0] = prmt(w01.x, w01.y, PRMT_LO);
        qh[ks][1] = prmt(w45.x, w45.y, PRMT_HI); ql[ks][1] = prmt(w45.x, w45.y, PRMT_LO);
        qh[ks][2] = prmt(w23.x, w23.y, PRMT_HI); ql[ks][2] = prmt(w23.x, w23.y, PRMT_LO);
        qh[ks][3] = prmt(w67.x, w67.y, PRMT_HI); ql[ks][3] = prmt(w67.x, w67.y, PRMT_LO);
    }

    float o[8][4];
#pragma unroll
    for (int j = 0; j < 8; j++)
#pragma unroll
        for (int r = 0; r < 4; r++) o[j][r] = 0.f;
    float mrow[2] = { -INFINITY, -INFINITY };
    float lrow[2] = { 0.f, 0.f };

    for (int kb = 0; kb <= qb; kb++) {
        const int buf = kb & 1;
        if (kb < qb) {
            loadKV(buf ^ 1, kb + 1);
            CP_COMMIT();
            CP_WAIT(1);
        } else {
            CP_WAIT(0);
        }
        __syncthreads();

        // S = Q @ K^T  (16 n-tiles of 8)
        float s[16][4];
#pragma unroll
        for (int j = 0; j < 16; j++)
#pragma unroll
            for (int r = 0; r < 4; r++) s[j][r] = 0.f;

#pragma unroll
        for (int ks = 0; ks < 4; ks++) {
#pragma unroll
            for (int jn = 0; jn < 16; jn++) {
                const uint32_t* b = Ks[buf] + (jn * 8 + g) * 72 + ks * 16 + 2 * t4;
                uint2 w01 = *(const uint2*)(b);
                uint2 w23 = *(const uint2*)(b + 8);
                uint32_t bh[2] = { prmt(w01.x, w01.y, PRMT_HI), prmt(w23.x, w23.y, PRMT_HI) };
                uint32_t bl[2] = { prmt(w01.x, w01.y, PRMT_LO), prmt(w23.x, w23.y, PRMT_LO) };
                mma16816(s[jn], qh[ks], bl);
                mma16816(s[jn], ql[ks], bh);
                mma16816(s[jn], qh[ks], bh);
            }
        }

        // causal mask on diagonal block
        if (kb == qb) {
            const int rowg = qb * 128 + warp * 16 + g;
#pragma unroll
            for (int jn = 0; jn < 16; jn++) {
                int col = kb * 128 + jn * 8 + 2 * t4;
                if (col     > rowg)     s[jn][0] = -INFINITY;
                if (col + 1 > rowg)     s[jn][1] = -INFINITY;
                if (col     > rowg + 8) s[jn][2] = -INFINITY;
                if (col + 1 > rowg + 8) s[jn][3] = -INFINITY;
            }
        }

        // online softmax (two rows per thread: g and g+8)
        float pcorr[2];
#pragma unroll
        for (int r2 = 0; r2 < 2; r2++) {
            float mx = -INFINITY;
#pragma unroll
            for (int jn = 0; jn < 16; jn++)
                mx = fmaxf(mx, fmaxf(s[jn][2 * r2], s[jn][2 * r2 + 1]));
            mx = fmaxf(mx, __shfl_xor_sync(0xffffffffu, mx, 1));
            mx = fmaxf(mx, __shfl_xor_sync(0xffffffffu, mx, 2));
            float mnew = fmaxf(mrow[r2], mx);
            float corr = __expf(mrow[r2] - mnew);
            mrow[r2] = mnew;
            pcorr[r2] = corr;
            float sum = 0.f;
#pragma unroll
            for (int jn = 0; jn < 16; jn++) {
                float p0 = __expf(s[jn][2 * r2]     - mnew);
                float p1 = __expf(s[jn][2 * r2 + 1] - mnew);
                s[jn][2 * r2] = p0; s[jn][2 * r2 + 1] = p1;
                sum += p0 + p1;
            }
            sum += __shfl_xor_sync(0xffffffffu, sum, 1);
            sum += __shfl_xor_sync(0xffffffffu, sum, 2);
            lrow[r2] = lrow[r2] * corr + sum;
        }
#pragma unroll
        for (int j = 0; j < 8; j++) {
            o[j][0] *= pcorr[0]; o[j][1] *= pcorr[0];
            o[j][2] *= pcorr[1]; o[j][3] *= pcorr[1];
        }

        // PV: A = P (regs), B = V^T tile from smem
#pragma unroll
        for (int ks = 0; ks < 8; ks++) {
            uint32_t ph[4], pl[4];
            split2pack(s[2 * ks][0],     s[2 * ks][1],     ph[0], pl[0]);
            split2pack(s[2 * ks][2],     s[2 * ks][3],     ph[1], pl[1]);
            split2pack(s[2 * ks + 1][0], s[2 * ks + 1][1], ph[2], pl[2]);
            split2pack(s[2 * ks + 1][2], s[2 * ks + 1][3], ph[3], pl[3]);
#pragma unroll
            for (int j2 = 0; j2 < 8; j2++) {
                const uint32_t* b = Vs[buf] + (j2 * 8 + g) * 136 + ks * 16 + 2 * t4;
                uint2 w01 = *(const uint2*)(b);
                uint2 w23 = *(const uint2*)(b + 8);
                uint32_t bh[2] = { prmt(w01.x, w01.y, PRMT_HI), prmt(w23.x, w23.y, PRMT_HI) };
                uint32_t bl[2] = { prmt(w01.x, w01.y, PRMT_LO), prmt(w23.x, w23.y, PRMT_LO) };
                mma16816(o[j2], ph, bl);
                mma16816(o[j2], pl, bh);
                mma16816(o[j2], ph, bh);
            }
        }
        __syncthreads();
    }

    // epilogue: y = o / l, write packed split
    const float inv0 = 1.0f / lrow[0];
    const float inv1 = 1.0f / lrow[1];
    const int row0 = qb * 128 + warp * 16 + g;
#pragma unroll
    for (int j2 = 0; j2 < 8; j2++) {
        int col = h * HDD + j2 * 8 + 2 * t4;
        y_s[(long long)row0 * DD + col]           = split_pack(o[j2][0] * inv0);
        y_s[(long long)row0 * DD + col + 1]       = split_pack(o[j2][1] * inv0);
        y_s[(long long)(row0 + 8) * DD + col]     = split_pack(o[j2][2] * inv1);
        y_s[(long long)(row0 + 8) * DD + col + 1] = split_pack(o[j2][3] * inv1);
    }
}

// ---------------- launch ----------------
extern "C" void kernel_launch(void* const* d_in, const int* in_sizes, int n_in,
                              void* d_out, int out_size) {
    const int*   idx        = (const int*)  d_in[0];
    const float* wte        = (const float*)d_in[1];
    const float* ln1_w      = (const float*)d_in[2];
    const float* attn_w     = (const float*)d_in[3];
    const float* attnproj_w = (const float*)d_in[4];
    const float* ln2_w      = (const float*)d_in[5];
    const float* fc_w       = (const float*)d_in[6];
    const float* fc_b       = (const float*)d_in[7];
    const float* proj_w     = (const float*)d_in[8];
    const float* proj_b     = (const float*)d_in[9];
    const float* lnf_w      = (const float*)d_in[10];
    const float* unemb_b    = (const float*)d_in[11];
    float* out = (float*)d_out;

    float *px, *pqkv;
    uint32_t *ph_s, *pqkv_s, *pvt_s, *py_s, *pm_s;
    uint32_t *pw_attn, *pw_aproj, *pw_fc, *pw_proj, *pw_wte;
    cudaGetSymbolAddress((void**)&px,      g_x);
    cudaGetSymbolAddress((void**)&ph_s,    g_h_s);
    cudaGetSymbolAddress((void**)&pqkv,    g_qkv);
    cudaGetSymbolAddress((void**)&pqkv_s,  g_qkv_s);
    cudaGetSymbolAddress((void**)&pvt_s,   g_vt_s);
    cudaGetSymbolAddress((void**)&py_s,    g_y_s);
    cudaGetSymbolAddress((void**)&pm_s,    g_m_s);
    cudaGetSymbolAddress((void**)&pw_attn,  g_ws_attn);
    cudaGetSymbolAddress((void**)&pw_aproj, g_ws_aproj);
    cudaGetSymbolAddress((void**)&pw_fc,    g_ws_fc);
    cudaGetSymbolAddress((void**)&pw_proj,  g_ws_proj);
    cudaGetSymbolAddress((void**)&pw_wte,   g_ws_wte);

    const int SM_GEMM  = 4 * 5120 * 4;               // 81920
    const int SM_FLASH = (9216 + 2 * 9216 + 2 * 8704) * 4;  // 180224
    cudaFuncSetAttribute(gemm3_kernel, cudaFuncAttributeMaxDynamicSharedMemorySize, SM_GEMM);
    cudaFuncSetAttribute(flash_kernel, cudaFuncAttributeMaxDynamicSharedMemorySize, SM_FLASH);

    auto split = [&](const float* s, uint32_t* d, long long n) {
        int n4 = (int)(n / 4);
        split_kernel<<<(n4 + 255) / 256, 256>>>((const float4*)s, (uint4*)d, n4);
    };
    split(attn_w,     pw_attn,  (long long)LL * 3 * DD * DD);
    split(attnproj_w, pw_aproj, (long long)LL * DD * DD);
    split(fc_w,       pw_fc,    (long long)LL * 4 * DD * DD);
    split(proj_w,     pw_proj,  (long long)LL * DD * 4 * DD);
    split(wte,        pw_wte,   (long long)VV * DD);

    embed_kernel<<<TT, 256>>>(idx, wte, px);

    for (int l = 0; l < LL; l++) {
        ln_split_kernel<<<TT, 256>>>(px, ln1_w + l * DD, ph_s);

        // QKV
        gemm3_kernel<<<dim3(3 * DD / 128, TT / 128), 256, SM_GEMM>>>(
            ph_s, DD, pw_attn + (long long)l * 3 * DD * DD, DD,
            pqkv, nullptr, 3 * DD, nullptr, nullptr, DD, 0);

        rope_split_kernel<<<(TT * NHH * 32 + 255) / 256, 256>>>(pqkv, pqkv_s);
        vsplit_t_kernel<<<(TT * DD + 255) / 256, 256>>>(pqkv, pvt_s);

        // fused attention -> y_s (packed)
        flash_kernel<<<dim3(TT / 128, NHH), 256, SM_FLASH>>>(pqkv_s, pvt_s, py_s);

        // x += y @ attnproj^T
        gemm3_kernel<<<dim3(DD / 128, TT / 128), 256, SM_GEMM>>>(
            py_s, DD, pw_aproj + (long long)l * DD * DD, DD,
            px, nullptr, DD, px, nullptr, DD, 0);

        ln_split_kernel<<<TT, 256>>>(px, ln2_w + l * DD, ph_s);

        // m = gelu(h @ fc^T + b) -> packed
        gemm3_kernel<<<dim3(4 * DD / 128, TT / 128), 256, SM_GEMM>>>(
            ph_s, DD, pw_fc + (long long)l * 4 * DD * DD, DD,
            nullptr, pm_s, 4 * DD, nullptr, fc_b + (long long)l * 4 * DD, DD,
            FLAG_GELU | FLAG_SPLIT);

        // x += m @ proj^T + b
        gemm3_kernel<<<dim3(DD / 128, TT / 128), 256, SM_GEMM>>>(
            pm_s, 4 * DD, pw_proj + (long long)l * DD * 4 * DD, 4 * DD,
            px, nullptr, DD, px, proj_b + (long long)l * DD, 4 * DD, 0);
    }

    ln_split_kernel<<<TT, 256>>>(px, lnf_w, ph_s);

    // logits
    gemm3_kernel<<<dim3(VV / 128, TT / 128), 256, SM_GEMM>>>(
        ph_s, DD, pw_wte, DD,
        out, nullptr, VV, nullptr, unemb_b, DD, 0);
}

// round 12
// speedup vs baseline: 1.5325x; 1.0022x over previous
#include <cuda_runtime.h>
#include <cuda_bf16.h>
#include <math.h>
#include <stdint.h>

#define TT   2048
#define DD   768
#define NHH  12
#define HDD  64
#define LL   4
#define VV   32000

#define FLAG_GELU   1
#define FLAG_SPLIT  8

#define PRMT_HI 0x7632
#define PRMT_LO 0x5410

// ---------------- scratch ----------------
__device__ __align__(128) float    g_x    [TT * DD];
__device__ __align__(128) uint32_t g_h_s  [TT * DD];
__device__ __align__(128) float    g_qkv  [TT * 3 * DD];
__device__ __align__(128) uint32_t g_qkv_s[TT * 3 * DD];
__device__ __align__(128) uint32_t g_vt_s [NHH * HDD * TT];
__device__ __align__(128) uint32_t g_y_s  [TT * DD];
__device__ __align__(128) uint32_t g_m_s  [TT * 4 * DD];
// split weights (packed hi<<16|lo)
__device__ __align__(128) uint32_t g_ws_attn [LL * 3 * DD * DD];
__device__ __align__(128) uint32_t g_ws_aproj[LL * DD * DD];
__device__ __align__(128) uint32_t g_ws_fc   [LL * 4 * DD * DD];
__device__ __align__(128) uint32_t g_ws_proj [LL * DD * 4 * DD];
__device__ __align__(128) uint32_t g_ws_wte  [VV * DD];

// ---------------- helpers ----------------
__device__ __forceinline__ uint32_t prmt(uint32_t a, uint32_t b, uint32_t s) {
    uint32_t d;
    asm("prmt.b32 %0, %1, %2, %3;" : "=r"(d) : "r"(a), "r"(b), "r"(s));
    return d;
}

__device__ __forceinline__ uint32_t split_pack(float x) {
    __nv_bfloat16 h = __float2bfloat16(x);
    float r = x - __bfloat162float(h);
    __nv_bfloat16 l = __float2bfloat16(r);
    return ((uint32_t)__bfloat16_as_ushort(h) << 16) | (uint32_t)__bfloat16_as_ushort(l);
}

// pack two floats into A-frag style bf16x2 regs (hi pair, lo pair); low half = s0
__device__ __forceinline__ void split2pack(float s0, float s1, uint32_t& hi, uint32_t& lo) {
    __nv_bfloat16 h0 = __float2bfloat16(s0);
    __nv_bfloat16 h1 = __float2bfloat16(s1);
    __nv_bfloat16 l0 = __float2bfloat16(s0 - __bfloat162float(h0));
    __nv_bfloat16 l1 = __float2bfloat16(s1 - __bfloat162float(h1));
    hi = ((uint32_t)__bfloat16_as_ushort(h1) << 16) | (uint32_t)__bfloat16_as_ushort(h0);
    lo = ((uint32_t)__bfloat16_as_ushort(l1) << 16) | (uint32_t)__bfloat16_as_ushort(l0);
}

__device__ __forceinline__ uint32_t smem_u32(const void* p) {
    return (uint32_t)__cvta_generic_to_shared(p);
}

__device__ __forceinline__ void cp16(uint32_t saddr, const void* g) {
    asm volatile("cp.async.cg.shared.global [%0], [%1], 16;" :: "r"(saddr), "l"(g));
}
#define CP_COMMIT() asm volatile("cp.async.commit_group;")
#define CP_WAIT(n)  asm volatile("cp.async.wait_group %0;" :: "n"(n))

__device__ __forceinline__ void mma16816(float* c, const uint32_t* a, const uint32_t* b) {
    asm volatile(
        "mma.sync.aligned.m16n8k16.row.col.f32.bf16.bf16.f32 "
        "{%0,%1,%2,%3}, {%4,%5,%6,%7}, {%8,%9}, {%0,%1,%2,%3};"
        : "+f"(c[0]), "+f"(c[1]), "+f"(c[2]), "+f"(c[3])
        : "r"(a[0]), "r"(a[1]), "r"(a[2]), "r"(a[3]), "r"(b[0]), "r"(b[1]));
}

__device__ __forceinline__ float blockReduceSum256(float v, float* red) {
#pragma unroll
    for (int o = 16; o; o >>= 1) v += __shfl_xor_sync(0xffffffffu, v, o);
    if ((threadIdx.x & 31) == 0) red[threadIdx.x >> 5] = v;
    __syncthreads();
    float t = 0.f;
#pragma unroll
    for (int i = 0; i < 8; i++) t += red[i];
    __syncthreads();
    return t;
}

// ---------------- elementwise kernels ----------------
__global__ void split_kernel(const float4* __restrict__ src, uint4* __restrict__ dst, int n4) {
    int i = blockIdx.x * blockDim.x + threadIdx.x;
    if (i >= n4) return;
    float4 v = src[i];
    uint4 o;
    o.x = split_pack(v.x); o.y = split_pack(v.y);
    o.z = split_pack(v.z); o.w = split_pack(v.w);
    dst[i] = o;
}

__global__ void embed_kernel(const int* __restrict__ idx,
                             const float* __restrict__ wte,
                             float* __restrict__ x) {
    int t = blockIdx.x;
    long long v = idx[t];
    const float* src = wte + v * DD;
    float* dst = x + (long long)t * DD;
    for (int d = threadIdx.x; d < DD; d += blockDim.x) dst[d] = src[d];
}

__global__ void ln_split_kernel(const float* __restrict__ x,
                                const float* __restrict__ w,
                                uint32_t* __restrict__ out) {
    __shared__ float red[8];
    int t = blockIdx.x;
    const float* xr = x + (long long)t * DD;
    int tid = threadIdx.x;
    float v0 = xr[tid], v1 = xr[tid + 256], v2 = xr[tid + 512];
    float sum = blockReduceSum256(v0 + v1 + v2, red);
    float mu = sum * (1.0f / DD);
    float d0 = v0 - mu, d1 = v1 - mu, d2 = v2 - mu;
    float sq = blockReduceSum256(d0 * d0 + d1 * d1 + d2 * d2, red);
    float inv = rsqrtf(sq * (1.0f / DD) + 1e-5f);
    uint32_t* o = out + (long long)t * DD;
    o[tid]       = split_pack(d0 * inv * w[tid]);
    o[tid + 256] = split_pack(d1 * inv * w[tid + 256]);
    o[tid + 512] = split_pack(d2 * inv * w[tid + 512]);
}

// RoPE + split; q additionally scaled by 1/8 (softmax scale folded in)
__global__ void rope_split_kernel(const float* __restrict__ qkv,
                                  uint32_t* __restrict__ qkv_s) {
    int gid = blockIdx.x * blockDim.x + threadIdx.x;
    if (gid >= TT * NHH * 32) return;
    int d = gid & 31;
    int h = (gid >> 5) % NHH;
    int t = gid / (NHH * 32);
    float inv = expf(-logf(10000.0f) * (float)d / 32.0f);
    float fr = (float)t * inv;
    float s, c;
    sincosf(fr, &s, &c);
    long long base = (long long)t * (3 * DD) + h * HDD;
    const float* q = qkv + base;
    uint32_t* qs = qkv_s + base;
    float q1 = q[d], q2 = q[d + 32];
    qs[d]      = split_pack((q1 * c - q2 * s) * 0.125f);
    qs[d + 32] = split_pack((q1 * s + q2 * c) * 0.125f);
    const float* k = q + DD;
    uint32_t* ks = qs + DD;
    float k1 = k[d], k2 = k[d + 32];
    ks[d]      = split_pack(k1 * c - k2 * s);
    ks[d + 32] = split_pack(k1 * s + k2 * c);
}

__global__ void vsplit_t_kernel(const float* __restrict__ qkv,
                                uint32_t* __restrict__ vt) {
    int id = blockIdx.x * blockDim.x + threadIdx.x;
    if (id >= TT * DD) return;
    int t = id & (TT - 1);
    int dg = id >> 11;
    vt[(long long)dg * TT + t] =
        split_pack(qkv[(long long)t * (3 * DD) + 2 * DD + dg]);
}

// ---------------- bf16x3 mma.sync GEMM (weight GEMMs) ----------------
__global__ void __launch_bounds__(256, 1)
gemm3_kernel(const uint32_t* __restrict__ A, int lda,
             const uint32_t* __restrict__ B, int ldb,
             float* __restrict__ Cf, uint32_t* __restrict__ Cu,
             int ldc,
             const float* __restrict__ Cin, const float* __restrict__ bias,
             int K, int flags) {
    const int bx = blockIdx.x, by = blockIdx.y;
    const int nk = K >> 5;

    extern __shared__ uint32_t sm[];
    uint32_t* As[2] = { sm, sm + 5120 };
    uint32_t* Bs[2] = { sm + 10240, sm + 10240 + 5120 };

    const int tid = threadIdx.x;
    const int lane = tid & 31, warp = tid >> 5;
    const int warpM = warp >> 2, warpN = warp & 3;
    const int g = lane >> 2, t4 = lane & 3;
    const int rA = warpM * 64;
    const int cB = warpN * 32;

    const uint32_t* Abase = A + (long long)(by * 128) * lda;
    const uint32_t* Bbase = B + (long long)(bx * 128) * ldb;

    auto load_stage = [&](uint32_t* Ad, uint32_t* Bd, int kc) {
        const uint32_t* Ag = Abase + kc * 32;
        const uint32_t* Bg = Bbase + kc * 32;
#pragma unroll
        for (int i = 0; i < 4; i++) {
            int id = tid + i * 256;
            int r = id >> 3, c = (id & 7) * 4;
            cp16(smem_u32(Ad + r * 40 + c), Ag + (long long)r * lda + c);
            cp16(smem_u32(Bd + r * 40 + c), Bg + (long long)r * ldb + c);
        }
    };

    float acc[4][4][4];
#pragma unroll
    for (int i = 0; i < 4; i++)
#pragma unroll
        for (int j = 0; j < 4; j++)
#pragma unroll
            for (int r = 0; r < 4; r++) acc[i][j][r] = 0.f;

    load_stage(As[0], Bs[0], 0);
    CP_COMMIT();

    for (int kc = 0; kc < nk; kc++) {
        const int cur = kc & 1;
        if (kc + 1 < nk) {
            load_stage(As[cur ^ 1], Bs[cur ^ 1], kc + 1);
            CP_COMMIT();
            CP_WAIT(1);
        } else {
            CP_WAIT(0);
        }
        __syncthreads();

        const uint32_t* Ac = As[cur];
        const uint32_t* Bc = Bs[cur];

#pragma unroll
        for (int kb = 0; kb < 32; kb += 16) {
            uint32_t ah[4][4], al[4][4];
#pragma unroll
            for (int i = 0; i < 4; i++) {
                const uint32_t* base = Ac + (rA + i * 16 + g) * 40 + kb + 2 * t4;
                uint2 w01 = *(const uint2*)(base);
                uint2 w23 = *(const uint2*)(base + 8);
                uint2 w45 = *(const uint2*)(base + 8 * 40);
                uint2 w67 = *(const uint2*)(base + 8 * 40 + 8);
                ah[i][0] = prmt(w01.x, w01.y, PRMT_HI); al[i][0] = prmt(w01.x, w01.y, PRMT_LO);
                ah[i][1] = prmt(w45.x, w45.y, PRMT_HI); al[i][1] = prmt(w45.x, w45.y, PRMT_LO);
                ah[i][2] = prmt(w23.x, w23.y, PRMT_HI); al[i][2] = prmt(w23.x, w23.y, PRMT_LO);
                ah[i][3] = prmt(w67.x, w67.y, PRMT_HI); al[i][3] = prmt(w67.x, w67.y, PRMT_LO);
            }
            uint32_t bh[4][2], bl[4][2];
#pragma unroll
            for (int j = 0; j < 4; j++) {
                const uint32_t* base = Bc + (cB + j * 8 + g) * 40 + kb + 2 * t4;
                uint2 w01 = *(const uint2*)(base);
                uint2 w23 = *(const uint2*)(base + 8);
                bh[j][0] = prmt(w01.x, w01.y, PRMT_HI); bl[j][0] = prmt(w01.x, w01.y, PRMT_LO);
                bh[j][1] = prmt(w23.x, w23.y, PRMT_HI); bl[j][1] = prmt(w23.x, w23.y, PRMT_LO);
            }
#pragma unroll
            for (int i = 0; i < 4; i++)
#pragma unroll
                for (int j = 0; j < 4; j++) mma16816(acc[i][j], ah[i], bl[j]);
#pragma unroll
            for (int i = 0; i < 4; i++)
#pragma unroll
                for (int j = 0; j < 4; j++) mma16816(acc[i][j], al[i], bh[j]);
#pragma unroll
            for (int i = 0; i < 4; i++)
#pragma unroll
                for (int j = 0; j < 4; j++) mma16816(acc[i][j], ah[i], bh[j]);
        }
        __syncthreads();
    }

    const bool gelu = flags & FLAG_GELU;
    const bool splitout = flags & FLAG_SPLIT;
#pragma unroll
    for (int i = 0; i < 4; i++) {
        int r0 = by * 128 + rA + i * 16 + g;
#pragma unroll
        for (int j = 0; j < 4; j++) {
            int c0 = bx * 128 + cB + j * 8 + 2 * t4;
#pragma unroll
            for (int r = 0; r < 4; r++) {
                int row = r0 + (r >> 1) * 8;
                int col = c0 + (r & 1);
                float v = acc[i][j][r];
                if (bias) v += bias[col];
                if (gelu) v = 0.5f * v * (1.0f + erff(v * 0.70710678118654752f));
                long long cidx = (long long)row * ldc + col;
                if (Cin) v += Cin[cidx];
                if (splitout) Cu[cidx] = split_pack(v);
                else          Cf[cidx] = v;
            }
        }
    }
}

// ---------------- fused flash attention (bf16x3 mma.sync) ----------------
// grid: (T/128, NH). CTA: 8 warps; each warp owns 16 q-rows x all 64 d.
__global__ void __launch_bounds__(256, 1)
flash_kernel(const uint32_t* __restrict__ qkv_s,
             const uint32_t* __restrict__ vt_s,
             uint32_t* __restrict__ y_s) {
    const int qb = (int)(gridDim.x - 1) - blockIdx.x;   // heavy blocks first
    const int h  = blockIdx.y;

    extern __shared__ uint32_t sm[];
    uint32_t* Qs = sm;                                   // 128 x 72
    uint32_t* Ks[2] = { sm + 9216, sm + 9216 + 9216 };   // 128 x 72 each
    uint32_t* Vs[2] = { sm + 27648, sm + 27648 + 8704 }; // 64 x 136 each

    const int tid = threadIdx.x;
    const int lane = tid & 31, warp = tid >> 5;
    const int g = lane >> 2, t4 = lane & 3;

    const uint32_t* Qg = qkv_s + (long long)(qb * 128) * (3 * DD) + h * HDD;
    const uint32_t* Kg = qkv_s + DD + h * HDD;
    const uint32_t* Vg = vt_s + (long long)(h * HDD) * TT;

    auto loadKV = [&](int buf, int kb) {
        const uint32_t* kg = Kg + (long long)(kb * 128) * (3 * DD);
#pragma unroll
        for (int i = 0; i < 8; i++) {
            int id = tid + i * 256;
            int r = id >> 4, c = (id & 15) * 4;
            cp16(smem_u32(Ks[buf] + r * 72 + c), kg + (long long)r * (3 * DD) + c);
        }
        const uint32_t* vg = Vg + kb * 128;
#pragma unroll
        for (int i = 0; i < 8; i++) {
            int id = tid + i * 256;
            int r = id >> 5, c = (id & 31) * 4;
            cp16(smem_u32(Vs[buf] + r * 136 + c), vg + (long long)r * TT + c);
        }
    };

    // load Q + first K/V block
#pragma unroll
    for (int i = 0; i < 8; i++) {
        int id = tid + i * 256;
        int r = id >> 4, c = (id & 15) * 4;
        cp16(smem_u32(Qs + r * 72 + c), Qg + (long long)r * (3 * DD) + c);
    }
    loadKV(0, 0);
    CP_COMMIT();
    CP_WAIT(0);
    __syncthreads();

    // Q fragments (persistent)
    uint32_t qh[4][4], ql[4][4];
#pragma unroll
    for (int ks = 0; ks < 4; ks++) {
        const uint32_t* base = Qs + (warp * 16 + g) * 72 + ks * 16 + 2 * t4;
        uint2 w01 = *(const uint2*)(base);
        uint2 w23 = *(const uint2*)(base + 8);
        uint2 w45 = *(const uint2*)(base + 8 * 72);
        uint2 w67 = *(const uint2*)(base + 8 * 72 + 8);
        qh[ks][0] = prmt(w01.x, w01.y, PRMT_HI); ql[ks][0] = prmt(w01.x, w01.y, PRMT_LO);
        qh[ks][1] = prmt(w45.x, w45.y, PRMT_HI); ql[ks][1] = prmt(w45.x, w45.y, PRMT_LO);
        qh[ks][2] = prmt(w23.x, w23.y, PRMT_HI); ql[ks][2] = prmt(w23.x, w23.y, PRMT_LO);
        qh[ks][3] = prmt(w67.x, w67.y, PRMT_HI); ql[ks][3] = prmt(w67.x, w67.y, PRMT_LO);
    }

    float o[8][4];
#pragma unroll
    for (int j = 0; j < 8; j++)
#pragma unroll
        for (int r = 0; r < 4; r++) o[j][r] = 0.f;
    float mrow[2] = { -INFINITY, -INFINITY };
    float lrow[2] = { 0.f, 0.f };

    for (int kb = 0; kb <= qb; kb++) {
        const int buf = kb & 1;
        if (kb < qb) {
            loadKV(buf ^ 1, kb + 1);
            CP_COMMIT();
            CP_WAIT(1);
        } else {
            CP_WAIT(0);
        }
        __syncthreads();

        // S = Q @ K^T  (16 n-tiles of 8)
        float s[16][4];
#pragma unroll
        for (int j = 0; j < 16; j++)
#pragma unroll
            for (int r = 0; r < 4; r++) s[j][r] = 0.f;

#pragma unroll
        for (int ks = 0; ks < 4; ks++) {
#pragma unroll
            for (int jn = 0; jn < 16; jn++) {
                const uint32_t* b = Ks[buf] + (jn * 8 + g) * 72 + ks * 16 + 2 * t4;
                uint2 w01 = *(const uint2*)(b);
                uint2 w23 = *(const uint2*)(b + 8);
                uint32_t bh[2] = { prmt(w01.x, w01.y, PRMT_HI), prmt(w23.x, w23.y, PRMT_HI) };
                uint32_t bl[2] = { prmt(w01.x, w01.y, PRMT_LO), prmt(w23.x, w23.y, PRMT_LO) };
                mma16816(s[jn], qh[ks], bl);
                mma16816(s[jn], ql[ks], bh);
                mma16816(s[jn], qh[ks], bh);
            }
        }

        // causal mask on diagonal block
        if (kb == qb) {
            const int rowg = qb * 128 + warp * 16 + g;
#pragma unroll
            for (int jn = 0; jn < 16; jn++) {
                int col = kb * 128 + jn * 8 + 2 * t4;
                if (col     > rowg)     s[jn][0] = -INFINITY;
                if (col + 1 > rowg)     s[jn][1] = -INFINITY;
                if (col     > rowg + 8) s[jn][2] = -INFINITY;
                if (col + 1 > rowg + 8) s[jn][3] = -INFINITY;
            }
        }

        // online softmax (two rows per thread: g and g+8)
        float pcorr[2];
#pragma unroll
        for (int r2 = 0; r2 < 2; r2++) {
            float mx = -INFINITY;
#pragma unroll
            for (int jn = 0; jn < 16; jn++)
                mx = fmaxf(mx, fmaxf(s[jn][2 * r2], s[jn][2 * r2 + 1]));
            mx = fmaxf(mx, __shfl_xor_sync(0xffffffffu, mx, 1));
            mx = fmaxf(mx, __shfl_xor_sync(0xffffffffu, mx, 2));
            float mnew = fmaxf(mrow[r2], mx);
            float corr = __expf(mrow[r2] - mnew);
            mrow[r2] = mnew;
            pcorr[r2] = corr;
            float sum = 0.f;
#pragma unroll
            for (int jn = 0; jn < 16; jn++) {
                float p0 = __expf(s[jn][2 * r2]     - mnew);
                float p1 = __expf(s[jn][2 * r2 + 1] - mnew);
                s[jn][2 * r2] = p0; s[jn][2 * r2 + 1] = p1;
                sum += p0 + p1;
            }
            sum += __shfl_xor_sync(0xffffffffu, sum, 1);
            sum += __shfl_xor_sync(0xffffffffu, sum, 2);
            lrow[r2] = lrow[r2] * corr + sum;
        }
#pragma unroll
        for (int j = 0; j < 8; j++) {
            o[j][0] *= pcorr[0]; o[j][1] *= pcorr[0];
            o[j][2] *= pcorr[1]; o[j][3] *= pcorr[1];
        }

        // PV: A = P (regs), B = V^T tile from smem
#pragma unroll
        for (int ks = 0; ks < 8; ks++) {
            uint32_t ph[4], pl[4];
            split2pack(s[2 * ks][0],     s[2 * ks][1],     ph[0], pl[0]);
            split2pack(s[2 * ks][2],     s[2 * ks][3],     ph[1], pl[1]);
            split2pack(s[2 * ks + 1][0], s[2 * ks + 1][1], ph[2], pl[2]);
            split2pack(s[2 * ks + 1][2], s[2 * ks + 1][3], ph[3], pl[3]);
#pragma unroll
            for (int j2 = 0; j2 < 8; j2++) {
                const uint32_t* b = Vs[buf] + (j2 * 8 + g) * 136 + ks * 16 + 2 * t4;
                uint2 w01 = *(const uint2*)(b);
                uint2 w23 = *(const uint2*)(b + 8);
                uint32_t bh[2] = { prmt(w01.x, w01.y, PRMT_HI), prmt(w23.x, w23.y, PRMT_HI) };
                uint32_t bl[2] = { prmt(w01.x, w01.y, PRMT_LO), prmt(w23.x, w23.y, PRMT_LO) };
                mma16816(o[j2], ph, bl);
                mma16816(o[j2], pl, bh);
                mma16816(o[j2], ph, bh);
            }
        }
        __syncthreads();
    }

    // epilogue: y = o / l, write packed split
    const float inv0 = 1.0f / lrow[0];
    const float inv1 = 1.0f / lrow[1];
    const int row0 = qb * 128 + warp * 16 + g;
#pragma unroll
    for (int j2 = 0; j2 < 8; j2++) {
        int col = h * HDD + j2 * 8 + 2 * t4;
        y_s[(long long)row0 * DD + col]           = split_pack(o[j2][0] * inv0);
        y_s[(long long)row0 * DD + col + 1]       = split_pack(o[j2][1] * inv0);
        y_s[(long long)(row0 + 8) * DD + col]     = split_pack(o[j2][2] * inv1);
        y_s[(long long)(row0 + 8) * DD + col + 1] = split_pack(o[j2][3] * inv1);
    }
}

// ---------------- launch ----------------
extern "C" void kernel_launch(void* const* d_in, const int* in_sizes, int n_in,
                              void* d_out, int out_size) {
    const int*   idx        = (const int*)  d_in[0];
    const float* wte        = (const float*)d_in[1];
    const float* ln1_w      = (const float*)d_in[2];
    const float* attn_w     = (const float*)d_in[3];
    const float* attnproj_w = (const float*)d_in[4];
    const float* ln2_w      = (const float*)d_in[5];
    const float* fc_w       = (const float*)d_in[6];
    const float* fc_b       = (const float*)d_in[7];
    const float* proj_w     = (const float*)d_in[8];
    const float* proj_b     = (const float*)d_in[9];
    const float* lnf_w      = (const float*)d_in[10];
    const float* unemb_b    = (const float*)d_in[11];
    float* out = (float*)d_out;

    float *px, *pqkv;
    uint32_t *ph_s, *pqkv_s, *pvt_s, *py_s, *pm_s;
    uint32_t *pw_attn, *pw_aproj, *pw_fc, *pw_proj, *pw_wte;
    cudaGetSymbolAddress((void**)&px,      g_x);
    cudaGetSymbolAddress((void**)&ph_s,    g_h_s);
    cudaGetSymbolAddress((void**)&pqkv,    g_qkv);
    cudaGetSymbolAddress((void**)&pqkv_s,  g_qkv_s);
    cudaGetSymbolAddress((void**)&pvt_s,   g_vt_s);
    cudaGetSymbolAddress((void**)&py_s,    g_y_s);
    cudaGetSymbolAddress((void**)&pm_s,    g_m_s);
    cudaGetSymbolAddress((void**)&pw_attn,  g_ws_attn);
    cudaGetSymbolAddress((void**)&pw_aproj, g_ws_aproj);
    cudaGetSymbolAddress((void**)&pw_fc,    g_ws_fc);
    cudaGetSymbolAddress((void**)&pw_proj,  g_ws_proj);
    cudaGetSymbolAddress((void**)&pw_wte,   g_ws_wte);

    const int SM_GEMM  = 4 * 5120 * 4;               // 81920
    const int SM_FLASH = (9216 + 2 * 9216 + 2 * 8704) * 4;  // 180224
    cudaFuncSetAttribute(gemm3_kernel, cudaFuncAttributeMaxDynamicSharedMemorySize, SM_GEMM);
    cudaFuncSetAttribute(flash_kernel, cudaFuncAttributeMaxDynamicSharedMemorySize, SM_FLASH);

    auto split = [&](const float* s, uint32_t* d, long long n) {
        int n4 = (int)(n / 4);
        split_kernel<<<(n4 + 255) / 256, 256>>>((const float4*)s, (uint4*)d, n4);
    };
    split(attn_w,     pw_attn,  (long long)LL * 3 * DD * DD);
    split(attnproj_w, pw_aproj, (long long)LL * DD * DD);
    split(fc_w,       pw_fc,    (long long)LL * 4 * DD * DD);
    split(proj_w,     pw_proj,  (long long)LL * DD * 4 * DD);
    split(wte,        pw_wte,   (long long)VV * DD);

    embed_kernel<<<TT, 256>>>(idx, wte, px);

    for (int l = 0; l < LL; l++) {
        ln_split_kernel<<<TT, 256>>>(px, ln1_w + l * DD, ph_s);

        // QKV
        gemm3_kernel<<<dim3(3 * DD / 128, TT / 128), 256, SM_GEMM>>>(
            ph_s, DD, pw_attn + (long long)l * 3 * DD * DD, DD,
            pqkv, nullptr, 3 * DD, nullptr, nullptr, DD, 0);

        rope_split_kernel<<<(TT * NHH * 32 + 255) / 256, 256>>>(pqkv, pqkv_s);
        vsplit_t_kernel<<<(TT * DD + 255) / 256, 256>>>(pqkv, pvt_s);

        // fused attention -> y_s (packed)
        flash_kernel<<<dim3(TT / 128, NHH), 256, SM_FLASH>>>(pqkv_s, pvt_s, py_s);

        // x += y @ attnproj^T
        gemm3_kernel<<<dim3(DD / 128, TT / 128), 256, SM_GEMM>>>(
            py_s, DD, pw_aproj + (long long)l * DD * DD, DD,
            px, nullptr, DD, px, nullptr, DD, 0);

        ln_split_kernel<<<TT, 256>>>(px, ln2_w + l * DD, ph_s);

        // m = gelu(h @ fc^T + b) -> packed
        gemm3_kernel<<<dim3(4 * DD / 128, TT / 128), 256, SM_GEMM>>>(
            ph_s, DD, pw_fc + (long long)l * 4 * DD * DD, DD,
            nullptr, pm_s, 4 * DD, nullptr, fc_b + (long long)l * 4 * DD, DD,
            FLAG_GELU | FLAG_SPLIT);

        // x += m @ proj^T + b
        gemm3_kernel<<<dim3(DD / 128, TT / 128), 256, SM_GEMM>>>(
            pm_s, 4 * DD, pw_proj + (long long)l * DD * 4 * DD, 4 * DD,
            px, nullptr, DD, px, proj_b + (long long)l * DD, 4 * DD, 0);
    }

    ln_split_kernel<<<TT, 256>>>(px, lnf_w, ph_s);

    // logits
    gemm3_kernel<<<dim3(VV / 128, TT / 128), 256, SM_GEMM>>>(
        ph_s, DD, pw_wte, DD,
        out, nullptr, VV, nullptr, unemb_b, DD, 0);
}